// round 6
// baseline (speedup 1.0000x reference)
#include <cuda_runtime.h>
#include <cstdint>

#define NN 50000
#define EE 800000
#define IND 128
#define HC 256      // HEADS*OUT_DIM
#define CC 64
#define HH 4
#define NEG_SLOPE 0.2f

// ---------------- device scratch ----------------------------------------------
__device__ float g_h[3ull * NN * HC];       // projected features per metapath
__device__ float g_asrc[3ull * NN * HH];
__device__ float g_adst[3ull * NN * HH];
__device__ float g_w[3ull * EE * HH];       // exp(leakyrelu(e)) per edge
__device__ float g_wl[3ull * NN * HH];      // self-loop numerators
__device__ float g_denom[3ull * NN * HH];
__device__ float g_acc[3ull * NN * CC];     // head-summed weighted aggregation

struct Ptrs {
    const float* W[3];
    const float* as[3];
    const float* ad[3];
    const int* ei[3];
};

__device__ __forceinline__ float lrelu(float v) {
    return v > 0.f ? v : NEG_SLOPE * v;
}

__device__ __forceinline__ void red_add_v4(float* addr, float4 v) {
    asm volatile("red.global.add.v4.f32 [%0], {%1,%2,%3,%4};"
                 :: "l"(addr), "f"(v.x), "f"(v.y), "f"(v.z), "f"(v.w)
                 : "memory");
}

// ---------------- fused GEMM (8x8 microtile) + attention-dot epilogue ---------
// grid: (ceil(N/128), 2, 3), block 256.
// Computes h = x@W for 128 rows x 128 cols (2 heads), writes g_h,
// then reduces a_src/a_dst per (row, head), writes g_asrc/g_adst,
// self-loop numerator g_wl, and atomically adds it into g_denom.
__global__ __launch_bounds__(256) void gemm_attn_kernel(const float* __restrict__ X, Ptrs P) {
    __shared__ float As[8][132];
    __shared__ float Bs[8][128];
    __shared__ float sAs[2][64], sAd[2][64];

    const int mp = blockIdx.z;
    const float* __restrict__ Wm = P.W[mp];
    const int tid = threadIdx.x;
    const int m0 = blockIdx.x * 128;
    const int n0 = blockIdx.y * 128;
    const int h0 = blockIdx.y * 2;

    if (tid < 128) {
        int p = tid >> 6, c = tid & 63;
        sAs[p][c] = P.as[mp][(h0 + p) * 64 + c];
        sAd[p][c] = P.ad[mp][(h0 + p) * 64 + c];
    }

    const int tx = tid & 15, ty = tid >> 4;

    float acc[8][8];
#pragma unroll
    for (int i = 0; i < 8; i++)
#pragma unroll
        for (int j = 0; j < 8; j++) acc[i][j] = 0.f;

    const int mrow = tid >> 1;           // 0..127
    const int kk = (tid & 1) * 4;        // 0 or 4
    const int bk = tid >> 5;             // 0..7
    const int bn = (tid & 31) * 4;       // 0..124
    const bool xvalid = (m0 + mrow) < NN;
    const float* xp = X + (size_t)(m0 + mrow) * IND + kk;

    for (int k0 = 0; k0 < IND; k0 += 8) {
        float4 xa = xvalid ? *(const float4*)(xp + k0) : make_float4(0.f, 0.f, 0.f, 0.f);
        __syncthreads();
        As[kk + 0][mrow] = xa.x; As[kk + 1][mrow] = xa.y;
        As[kk + 2][mrow] = xa.z; As[kk + 3][mrow] = xa.w;
        *(float4*)&Bs[bk][bn] = *(const float4*)&Wm[(size_t)(k0 + bk) * HC + n0 + bn];
        __syncthreads();
#pragma unroll
        for (int k = 0; k < 8; k++) {
            float a[8], b[8];
            *(float4*)&a[0] = *(float4*)&As[k][ty * 8];
            *(float4*)&a[4] = *(float4*)&As[k][ty * 8 + 4];
            *(float4*)&b[0] = *(float4*)&Bs[k][tx * 4];
            *(float4*)&b[4] = *(float4*)&Bs[k][64 + tx * 4];
#pragma unroll
            for (int i = 0; i < 8; i++)
#pragma unroll
                for (int j = 0; j < 8; j++) acc[i][j] += a[i] * b[j];
        }
    }

    // store h: cols j0..3 -> n0 + tx*4 (head h0), j4..7 -> n0 + 64 + tx*4 (head h0+1)
    float* __restrict__ Hout = g_h + (size_t)mp * NN * HC;
#pragma unroll
    for (int i = 0; i < 8; i++) {
        int m = m0 + ty * 8 + i;
        if (m < NN) {
            *(float4*)&Hout[(size_t)m * HC + n0 + tx * 4] = *(float4*)&acc[i][0];
            *(float4*)&Hout[(size_t)m * HC + n0 + 64 + tx * 4] = *(float4*)&acc[i][4];
        }
    }

    // attention dots + self loop
#pragma unroll
    for (int i = 0; i < 8; i++) {
        float vs0 = 0.f, vd0 = 0.f, vs1 = 0.f, vd1 = 0.f;
#pragma unroll
        for (int j = 0; j < 4; j++) {
            int c = tx * 4 + j;
            vs0 += acc[i][j] * sAs[0][c];
            vd0 += acc[i][j] * sAd[0][c];
            vs1 += acc[i][4 + j] * sAs[1][c];
            vd1 += acc[i][4 + j] * sAd[1][c];
        }
#pragma unroll
        for (int o = 8; o > 0; o >>= 1) {
            vs0 += __shfl_down_sync(0xffffffffu, vs0, o, 16);
            vd0 += __shfl_down_sync(0xffffffffu, vd0, o, 16);
            vs1 += __shfl_down_sync(0xffffffffu, vs1, o, 16);
            vd1 += __shfl_down_sync(0xffffffffu, vd1, o, 16);
        }
        if (tx == 0) {
            int m = m0 + ty * 8 + i;
            if (m < NN) {
                size_t base = (size_t)mp * NN * HH + (size_t)m * HH;
                g_asrc[base + h0] = vs0;
                g_asrc[base + h0 + 1] = vs1;
                g_adst[base + h0] = vd0;
                g_adst[base + h0 + 1] = vd1;
                float w0 = __expf(lrelu(vs0 + vd0));
                float w1 = __expf(lrelu(vs1 + vd1));
                g_wl[base + h0] = w0;
                g_wl[base + h0 + 1] = w1;
                atomicAdd(&g_denom[base + h0], w0);
                atomicAdd(&g_denom[base + h0 + 1], w1);
            }
        }
    }
}

// ---------------- edge pass 1: numerators + denom (z = metapath) --------------
__global__ void edge_softmax_kernel(Ptrs P) {
    int mp = blockIdx.z;
    const int* __restrict__ ei = P.ei[mp];
    int e = blockIdx.x * blockDim.x + threadIdx.x;
    if (e >= EE) return;
    int s = ei[e], d = ei[EE + e];
    const float* asrc = &g_asrc[(size_t)mp * NN * HH];
    const float* adst = &g_adst[(size_t)mp * NN * HH];
    float4 as = *(const float4*)&asrc[s * HH];
    float4 ad = *(const float4*)&adst[d * HH];
    float4 v;
    v.x = __expf(lrelu(as.x + ad.x));
    v.y = __expf(lrelu(as.y + ad.y));
    v.z = __expf(lrelu(as.z + ad.z));
    v.w = __expf(lrelu(as.w + ad.w));
    *(float4*)&g_w[(size_t)mp * EE * HH + (size_t)e * HH] = v;
    red_add_v4(&g_denom[(size_t)mp * NN * HH + d * HH], v);
}

// ---------------- edge pass 2: weighted aggregation (16 thr / edge) -----------
// alpha = w/denom[d] computed in-place here (denom[d] cache line is the same
// one the RED below targets, so the gather is effectively free).
__global__ void edge_agg_kernel(Ptrs P) {
    int mp = blockIdx.z;
    const int* __restrict__ ei = P.ei[mp];
    int t = blockIdx.x * blockDim.x + threadIdx.x;
    int e = t >> 4;
    int cg = (t & 15) * 4;
    if (e >= EE) return;
    int s = ei[e], d = ei[EE + e];
    float4 we = *(const float4*)&g_w[(size_t)mp * EE * HH + (size_t)e * HH];
    float4 de = *(const float4*)&g_denom[(size_t)mp * NN * HH + d * HH];
    float a0 = __fdividef(we.x, de.x);
    float a1 = __fdividef(we.y, de.y);
    float a2 = __fdividef(we.z, de.z);
    float a3 = __fdividef(we.w, de.w);
    const float* hp = &g_h[(size_t)mp * NN * HC + (size_t)s * HC];
    float4 h0 = *(const float4*)&hp[cg];
    float4 h1 = *(const float4*)&hp[CC + cg];
    float4 h2 = *(const float4*)&hp[2 * CC + cg];
    float4 h3 = *(const float4*)&hp[3 * CC + cg];
    float4 v;
    v.x = a0 * h0.x + a1 * h1.x + a2 * h2.x + a3 * h3.x;
    v.y = a0 * h0.y + a1 * h1.y + a2 * h2.y + a3 * h3.y;
    v.z = a0 * h0.z + a1 * h1.z + a2 * h2.z + a3 * h3.z;
    v.w = a0 * h0.w + a1 * h1.w + a2 * h2.w + a3 * h3.w;
    red_add_v4(&g_acc[(size_t)mp * NN * CC + (size_t)d * CC + cg], v);
}

// ---------------- finalize: elu + semantic attention --------------------------
__global__ void finalize_kernel(const float* __restrict__ proj_W,
                                const float* __restrict__ proj_b,
                                const float* __restrict__ attn_vec,
                                const float* __restrict__ bias0,
                                const float* __restrict__ bias1,
                                const float* __restrict__ bias2,
                                float* __restrict__ out, int write_beta) {
    __shared__ float Wsm[64 * 64];
    __shared__ float zs[4][3][64];
    __shared__ float sred[4][3];
    __shared__ float bsm[64], av[64], biasm[3][64];
    int tid = threadIdx.x;
    for (int i = tid; i < 64 * 64; i += 256) Wsm[i] = proj_W[i];
    if (tid < 64) {
        bsm[tid] = proj_b[tid];
        av[tid] = attn_vec[tid];
        biasm[0][tid] = bias0[tid];
        biasm[1][tid] = bias1[tid];
        biasm[2][tid] = bias2[tid];
    }
    __syncthreads();

    int g = tid >> 6, j = tid & 63;
    for (int n0 = blockIdx.x * 4; n0 < NN; n0 += gridDim.x * 4) {
        int n = n0 + g;
        bool valid = n < NN;
        float zreg[3] = {0.f, 0.f, 0.f};
        if (valid) {
#pragma unroll
            for (int m = 0; m < 3; m++) {
                float accv = g_acc[(size_t)m * NN * CC + (size_t)n * CC + j];
                float selfv = 0.f;
#pragma unroll
                for (int h = 0; h < HH; h++) {
                    float alpha = g_wl[(size_t)m * NN * HH + n * HH + h] /
                                  g_denom[(size_t)m * NN * HH + n * HH + h];
                    selfv += alpha * g_h[(size_t)m * NN * HC + (size_t)n * HC + h * CC + j];
                }
                float z = (accv + selfv) * 0.25f + biasm[m][j];
                z = z > 0.f ? z : (__expf(z) - 1.0f);
                zreg[m] = z;
                zs[g][m][j] = z;
            }
        } else {
            zs[g][0][j] = 0.f; zs[g][1][j] = 0.f; zs[g][2][j] = 0.f;
        }
        if (j < 3) sred[g][j] = 0.f;
        __syncthreads();

#pragma unroll
        for (int m = 0; m < 3; m++) {
            float t = bsm[j];
#pragma unroll
            for (int c = 0; c < 64; c++) t += zs[g][m][c] * Wsm[c * 64 + j];
            // fast tanh: 1 - 2/(e^{2t}+1), safe at +-inf
            float t2 = __expf(2.f * t);
            t = 1.f - __fdividef(2.f, t2 + 1.f);
            float p = t * av[j];
#pragma unroll
            for (int o = 16; o > 0; o >>= 1) p += __shfl_down_sync(0xffffffffu, p, o);
            if ((tid & 31) == 0) atomicAdd(&sred[g][m], p);
        }
        __syncthreads();

        float s0 = sred[g][0], s1 = sred[g][1], s2 = sred[g][2];
        float mx = fmaxf(s0, fmaxf(s1, s2));
        float e0 = __expf(s0 - mx), e1 = __expf(s1 - mx), e2 = __expf(s2 - mx);
        float inv = 1.0f / (e0 + e1 + e2);
        float b0 = e0 * inv, b1 = e1 * inv, b2 = e2 * inv;
        if (valid) {
            out[(size_t)n * CC + j] = b0 * zreg[0] + b1 * zreg[1] + b2 * zreg[2];
            if (write_beta && j < 3)
                out[(size_t)NN * CC + (size_t)n * 3 + j] = (j == 0 ? b0 : (j == 1 ? b1 : b2));
        }
        __syncthreads();
    }
}

// ---------------- launch ------------------------------------------------------
// Input order (setup_inputs insertion order):
//   0: x; 1+5i+{0..4}: edge_index_i, W_i, att_src_i, att_dst_i, bias_i;
//   16: proj_W, 17: proj_b, 18: attn_vec
extern "C" void kernel_launch(void* const* d_in, const int* in_sizes, int n_in,
                              void* d_out, int out_size) {
    const float* x = (const float*)d_in[0];
    Ptrs P;
    const float* bias[3];
    for (int i = 0; i < 3; i++) {
        P.ei[i] = (const int*)d_in[1 + 5 * i + 0];
        P.W[i]  = (const float*)d_in[1 + 5 * i + 1];
        P.as[i] = (const float*)d_in[1 + 5 * i + 2];
        P.ad[i] = (const float*)d_in[1 + 5 * i + 3];
        bias[i] = (const float*)d_in[1 + 5 * i + 4];
    }
    const float* projW = (const float*)d_in[16];
    const float* projb = (const float*)d_in[17];
    const float* attnv = (const float*)d_in[18];
    float* out = (float*)d_out;

    void *pd, *pa;
    cudaGetSymbolAddress(&pd, g_denom);
    cudaGetSymbolAddress(&pa, g_acc);
    cudaMemsetAsync(pd, 0, 3ull * NN * HH * sizeof(float), 0);
    cudaMemsetAsync(pa, 0, 3ull * NN * CC * sizeof(float), 0);

    dim3 gg((NN + 127) / 128, 2, 3);
    gemm_attn_kernel<<<gg, 256>>>(x, P);

    dim3 ge((EE + 255) / 256, 1, 3);
    edge_softmax_kernel<<<ge, 256>>>(P);

    dim3 ga((EE * 16) / 256, 1, 3);
    edge_agg_kernel<<<ga, 256>>>(P);

    int wb = (out_size >= NN * CC + NN * 3) ? 1 : 0;
    finalize_kernel<<<1024, 256>>>(projW, projb, attnv, bias[0], bias[1], bias[2], out, wb);
}